// round 14
// baseline (speedup 1.0000x reference)
#include <cuda_runtime.h>
#include <cuda_bf16.h>
#include <math.h>
#include <stdint.h>

#define NB_  32
#define NH_  64
#define ND_  512
#define NROPE_ 64
#define NHALF_ 32
#define SMAX_ 4096
#define BS_  64
#define IH_  64
#define ID_  128
#define TOPK_ 512
#define SCALE_ 0.04419417382415922f

typedef unsigned long long ull;

// ---------------- scratch ----------------
__device__ float    g_qr[NB_*NH_*ND_];
__device__ unsigned g_qq[NB_*IH_*32];
__device__ float    g_qs[NB_*IH_];
__device__ float    g_w[NB_*ID_];
__device__ float    g_iscore[NB_*SMAX_];
__device__ int      g_sel[NB_*TOPK_];
__device__ int      g_has0[NB_];
__device__ float    g_pO[NB_*4*2*16*512];
__device__ float2   g_pml[NB_*4*2*16];

// ---------------- helpers ----------------
__device__ __forceinline__ void mma_tf32(float& c0, float& c1, float& c2, float& c3,
                                         unsigned a0, unsigned a1, unsigned a2, unsigned a3,
                                         unsigned b0, unsigned b1) {
    asm volatile("mma.sync.aligned.m16n8k8.row.col.f32.tf32.tf32.f32 "
        "{%0,%1,%2,%3}, {%4,%5,%6,%7}, {%8,%9}, {%0,%1,%2,%3};"
        : "+f"(c0), "+f"(c1), "+f"(c2), "+f"(c3)
        : "r"(a0), "r"(a1), "r"(a2), "r"(a3), "r"(b0), "r"(b1));
}

__device__ __forceinline__ void cpa16(void* dst_s, const void* src) {
    unsigned ds = (unsigned)__cvta_generic_to_shared(dst_s);
    asm volatile("cp.async.cg.shared.global [%0], [%1], 16;" :: "r"(ds), "l"(src));
}
#define CP_COMMIT() asm volatile("cp.async.commit_group;")
#define CP_WAIT0()  asm volatile("cp.async.wait_group 0;")

#define SPLIT_HL(x, hi, lo) do { \
    hi = __float_as_uint(x) & 0xFFFFE000u; \
    lo = __float_as_uint((x) - __uint_as_float(hi)); \
} while(0)

// ---------------- kernel 1: fused rope + q_idx quant ----------------
__device__ __forceinline__ int quant1(float x, float scale) {
    float r = rintf(x / scale);
    r = fminf(fmaxf(r, -128.f), 127.f);
    return (int)r;
}

__device__ __forceinline__ float quantf(float x, float scale) {
    float r = rintf(x / scale);
    return fminf(fmaxf(r, -128.f), 127.f);
}

__global__ void prep_kernel(const float* __restrict__ q,
                            const float* __restrict__ cosp,
                            const float* __restrict__ sinp,
                            const float* __restrict__ q_idx) {
    int t = threadIdx.x;
    if (blockIdx.x < 1024) {
        int bh = blockIdx.x * 2 + (t >> 7);
        int b  = bh >> 6;
        int d  = (t & 127) * 4;
        const float* src = q + (size_t)bh * ND_;
        float4 v = *(const float4*)(src + d);
        float4 o;
        if (d < ND_ - NROPE_) {
            o = v;
        } else {
            int i0 = (d - (ND_ - NROPE_)) >> 1;
            float c0 = cosp[b*NHALF_ + i0],   s0 = sinp[b*NHALF_ + i0];
            float c1 = cosp[b*NHALF_ + i0+1], s1 = sinp[b*NHALF_ + i0+1];
            o.x = v.x*c0 - v.y*s0;
            o.y = v.x*s0 + v.y*c0;
            o.z = v.z*c1 - v.w*s1;
            o.w = v.z*s1 + v.w*c1;
        }
        *(float4*)(g_qr + (size_t)bh*ND_ + d) = o;
    } else {
        int row  = (blockIdx.x - 1024) * 8 + (t >> 5);
        int lane = t & 31;
        float4 v = *(const float4*)(q_idx + (size_t)row*ID_ + lane*4);
        float m = fmaxf(fmaxf(fabsf(v.x), fabsf(v.y)), fmaxf(fabsf(v.z), fabsf(v.w)));
        #pragma unroll
        for (int o = 16; o; o >>= 1) m = fmaxf(m, __shfl_xor_sync(0xffffffffu, m, o));
        float scale = fmaxf(m, 1e-12f) * (1.f/127.f);
        if (scale < 1e-6f) scale = 1.f;
        int q0 = quant1(v.x, scale), q1 = quant1(v.y, scale);
        int q2 = quant1(v.z, scale), q3 = quant1(v.w, scale);
        unsigned w = (q0 & 0xFF) | ((q1 & 0xFF) << 8) | ((q2 & 0xFF) << 16) | ((q3 & 0xFF) << 24);
        g_qq[row*32 + lane] = w;
        if (lane == 0) g_qs[row] = scale;
    }
}

// ---------------- kernel 1b: w[b][d] = sum_h qs_h * qq_h[d] ----------------
__global__ void wsum_kernel() {
    int b = blockIdx.x;
    int d = threadIdx.x;
    int wi  = d >> 2;
    int wsh = (d & 3) << 3;
    float acc = 0.f;
    #pragma unroll 8
    for (int h = 0; h < IH_; h++) {
        unsigned wv = g_qq[(b*IH_ + h)*32 + wi];
        int c = (int)((signed char)((wv >> wsh) & 0xFFu));
        acc = fmaf((float)c, g_qs[b*IH_ + h], acc);
    }
    g_w[b*ID_ + d] = acc;
}

// ---------------- kernel 2: indexer, one 128-dot per key ----------------
__global__ void __launch_bounds__(256)
indexer_kernel(const float* __restrict__ k_idx_cache,
               const int* __restrict__ btbl,
               const int* __restrict__ seq_lens) {
    __shared__ float sw[ID_];
    int b = blockIdx.y, chunk = blockIdx.x;
    int t = threadIdx.x;
    if (t < ID_) sw[t] = g_w[b*ID_ + t];
    __syncthreads();

    int seqlen = seq_lens[b];
    int s = chunk*256 + t;
    int cs = min(s, seqlen-1);
    int pg = btbl[(b << 6) + (cs >> 6)];
    const float4* kr = (const float4*)(k_idx_cache + ((size_t)pg*BS_ + (cs & 63)) * ID_);

    float mx = 0.f;
    #pragma unroll
    for (int i = 0; i < 32; i++) {
        float4 v = kr[i];
        mx = fmaxf(mx, fmaxf(fmaxf(fabsf(v.x), fabsf(v.y)), fmaxf(fabsf(v.z), fabsf(v.w))));
    }
    float scale = fmaxf(mx, 1e-12f) * (1.f/127.f);
    if (scale < 1e-6f) scale = 1.f;

    float tot = 0.f;
    #pragma unroll
    for (int i = 0; i < 32; i++) {
        float4 v = kr[i];
        float q0 = quantf(v.x, scale);
        float q1 = quantf(v.y, scale);
        float q2 = quantf(v.z, scale);
        float q3 = quantf(v.w, scale);
        tot = fmaf(q0, sw[i*4+0], tot);
        tot = fmaf(q1, sw[i*4+1], tot);
        tot = fmaf(q2, sw[i*4+2], tot);
        tot = fmaf(q3, sw[i*4+3], tot);
    }
    g_iscore[b*SMAX_ + s] = (s < seqlen) ? tot * scale : __int_as_float(0xff800000);
}

// ---------------- kernel 3: exact top-k, 1024 threads ----------------
__device__ __forceinline__ int exscan1024(int v, int* sh, int* total) {
    int t = threadIdx.x, lane = t & 31, wid = t >> 5;
    __syncthreads();
    int incl = v;
    #pragma unroll
    for (int o = 1; o < 32; o <<= 1) {
        int n = __shfl_up_sync(0xffffffffu, incl, o);
        if (lane >= o) incl += n;
    }
    if (lane == 31) sh[wid] = incl;
    __syncthreads();
    if (wid == 0) {
        int x = sh[lane];
        #pragma unroll
        for (int o = 1; o < 32; o <<= 1) {
            int n = __shfl_up_sync(0xffffffffu, x, o);
            if (lane >= o) x += n;
        }
        sh[lane] = x;
    }
    __syncthreads();
    int base = wid ? sh[wid-1] : 0;
    *total = sh[31];
    return base + incl - v;
}

__device__ __forceinline__ void select_bin(int* hist, int* sscan, int* sinfo, int Krem) {
    int t = threadIdx.x, lane = t & 31, wid = t >> 5;
    int c = (t < 256) ? hist[t] : 0;
    int incl = c;
    #pragma unroll
    for (int o = 1; o < 32; o <<= 1) {
        int n = __shfl_up_sync(0xffffffffu, incl, o);
        if (lane >= o) incl += n;
    }
    if (lane == 31 && wid < 8) sscan[wid] = incl;
    __syncthreads();
    if (wid == 0) {
        int x = (lane < 8) ? sscan[lane] : 0;
        #pragma unroll
        for (int o = 1; o < 8; o <<= 1) {
            int n = __shfl_up_sync(0xffffffffu, x, o);
            if (lane >= o) x += n;
        }
        if (lane < 8) sscan[lane] = x;
        if (lane == 7) sinfo[2] = x;
    }
    __syncthreads();
    if (t < 256) {
        int P = incl + (wid ? sscan[wid-1] : 0);
        int above = sinfo[2] - P;
        if (above < Krem && Krem <= above + c) {
            sinfo[0] = t;
            sinfo[1] = Krem - above;
        }
    }
    __syncthreads();
}

__global__ void __launch_bounds__(1024)
topk_kernel() {
    int b = blockIdx.x;
    __shared__ unsigned skey[SMAX_];
    __shared__ unsigned cand[SMAX_];
    __shared__ int hist[256];
    __shared__ int sscan[33];
    __shared__ int sinfo[3];
    __shared__ int ccnt;
    int t = threadIdx.x;   // 1024 threads

    {
        int i = t * 4;
        float4 v = *(const float4*)(g_iscore + b*SMAX_ + i);
        #pragma unroll
        for (int j = 0; j < 4; j++) {
            unsigned u = __float_as_uint((&v.x)[j]);
            skey[i+j] = (u & 0x80000000u) ? ~u : (u | 0x80000000u);
        }
    }
    if (t == 0) ccnt = 0;
    if (t < 256) hist[t] = 0;
    __syncthreads();

    for (int i = t; i < SMAX_; i += 1024)
        atomicAdd((unsigned*)&hist[skey[i] >> 24], 1u);
    __syncthreads();
    select_bin(hist, sscan, sinfo, TOPK_);
    unsigned b1 = (unsigned)sinfo[0];
    unsigned prefix = b1 << 24;
    int Krem = sinfo[1];

    for (int i = t; i < SMAX_; i += 1024) {
        unsigned u = skey[i];
        if ((u >> 24) == b1) cand[atomicAdd((unsigned*)&ccnt, 1u)] = u;
    }
    __syncthreads();
    int L = ccnt;
    unsigned mask = 0xFF000000u;

    for (int shift = 16; shift >= 0; shift -= 8) {
        if (t < 256) hist[t] = 0;
        __syncthreads();
        for (int i = t; i < L; i += 1024) {
            unsigned u = cand[i];
            if ((u & mask) == prefix) atomicAdd((unsigned*)&hist[(u >> shift) & 255], 1u);
        }
        __syncthreads();
        select_bin(hist, sscan, sinfo, Krem);
        prefix |= ((unsigned)sinfo[0]) << shift;
        mask   |= 0xFFu << shift;
        Krem = sinfo[1];
    }
    unsigned T = prefix;
    int R = Krem;

    int base = t * 4;
    int eqc = 0;
    #pragma unroll
    for (int i = 0; i < 4; i++) eqc += (skey[base+i] == T);
    int tot;
    int eqoff = exscan1024(eqc, sscan, &tot);

    int kc = 0;
    unsigned kmask = 0;
    int er = eqoff;
    #pragma unroll
    for (int i = 0; i < 4; i++) {
        unsigned u = skey[base+i];
        bool eq = (u == T);
        bool kp = (u > T) || (eq && er < R);
        er += eq;
        if (base + i == 0) g_has0[b] = kp ? 1 : 0;
        kmask |= (unsigned)kp << i;
        kc += kp;
    }
    int koff = exscan1024(kc, sscan, &tot);
    int p = koff;
    #pragma unroll
    for (int i = 0; i < 4; i++) {
        if ((kmask >> i) & 1) g_sel[b*TOPK_ + p++] = base + i;
    }
}

// ---------------- kernel 4: split-KV attention; A and C on tf32 MMA ----------------
#define QSTR 516
#define SCSTR 260

struct AttnSmem {
    float q[16*QSTR];        // 33024
    float k[2][64][128];     // 65536 swizzled
    float sc[16][SCSTR];     // 16640
};                           // 115200 B

extern __shared__ char smem_raw[];

__device__ __forceinline__ void prefetch_tile(AttnSmem& S, int buf, int tile, int ch,
                                              int selbase,
                                              const float* __restrict__ kv,
                                              const int* __restrict__ btbl,
                                              int bq, int t) {
    int kbase = tile << 6;
    int g = t & 31;
    int dstg = g ^ ((t >> 5) & 7);
    #pragma unroll
    for (int i = 0; i < 8; i++) {
        int r = (t >> 5) + (i << 3);
        int sp = g_sel[selbase + kbase + r];
        int pg = btbl[bq + (sp >> 6)];
        const float* src = kv + ((size_t)pg*BS_ + (sp & 63)) * ND_ + (ch << 7) + (g << 2);
        cpa16(&S.k[buf][r][dstg << 2], src);
    }
    CP_COMMIT();
}

__global__ void __launch_bounds__(256, 2)
attn_kernel(const float* __restrict__ kv,
            const float* __restrict__ attn_sink,
            const int* __restrict__ btbl) {
    AttnSmem& S = *(AttnSmem*)smem_raw;
    int hg = blockIdx.x, b = blockIdx.y, split = blockIdx.z;
    int t = threadIdx.x;
    int hbase = hg * 16;
    int selbase = b*TOPK_ + split*256;
    int bq = b << 6;
    int slot = (b*4 + hg)*2 + split;

    {
        const float* qr = g_qr + ((size_t)b*NH_ + hbase) * ND_;
        for (int i = t*4; i < 16*ND_; i += 1024) {
            int row = i >> 9, col = i & 511;
            *(float4*)&S.q[row*QSTR + col] = *(const float4*)(qr + i);
        }
    }
    prefetch_tile(S, 0, 0, 0, selbase, kv, btbl, bq, t);
    __syncthreads();

    int w    = t >> 5;
    int lane = t & 31;
    int g4 = lane >> 2, l4 = lane & 3;

    // ======== phase A: scores via tf32 MMA, 3 independent chains ========
    float Ahl[4], Alh[4], Ahh[4];
    int buf = 0;
    int rloc = (w << 3) + g4;
    #pragma unroll 1
    for (int s = 0; s < 16; s++) {
        CP_WAIT0();
        __syncthreads();
        if (s < 15) prefetch_tile(S, buf^1, (s+1) >> 2, (s+1) & 3, selbase, kv, btbl, bq, t);
        else        prefetch_tile(S, buf^1, 0, 0, selbase, kv, btbl, bq, t);
        int tile = s >> 2, ch = s & 3;
        if (ch == 0) {
            #pragma unroll
            for (int r = 0; r < 4; r++) { Ahl[r] = 0.f; Alh[r] = 0.f; Ahh[r] = 0.f; }
        }
        const float* kb  = &S.k[buf][rloc][0];
        const float* q0p = &S.q[g4*QSTR + (ch << 7) + l4];
        const float* q1p = &S.q[(g4+8)*QSTR + (ch << 7) + l4];
        #pragma unroll
        for (int ks = 0; ks < 16; ks++) {
            int k0 = ks << 3;
            float a0 = q0p[k0];
            float a1 = q1p[k0];
            float a2 = q0p[k0 + 4];
            float a3 = q1p[k0 + 4];
            int gb = k0 >> 2;
            float b0 = kb[((gb ^ g4) << 2) + l4];
            float b1 = kb[(((gb + 1) ^ g4) << 2) + l4];
            unsigned ah0, ah1, ah2, ah3, al0, al1, al2, al3, bh0, bh1, bl0, bl1;
            SPLIT_HL(a0, ah0, al0); SPLIT_HL(a1, ah1, al1);
            SPLIT_HL(a2, ah2, al2); SPLIT_HL(a3, ah3, al3);
            SPLIT_HL(b0, bh0, bl0); SPLIT_HL(b1, bh1, bl1);
            mma_tf32(Ahl[0],Ahl[1],Ahl[2],Ahl[3], ah0,ah1,ah2,ah3, bl0,bl1);
            mma_tf32(Alh[0],Alh[1],Alh[2],Alh[3], al0,al1,al2,al3, bh0,bh1);
            mma_tf32(Ahh[0],Ahh[1],Ahh[2],Ahh[3], ah0,ah1,ah2,ah3, bh0,bh1);
        }
        if (ch == 3) {
            int j0 = (tile << 6) + (w << 3) + (l4 << 1);
            S.sc[g4][j0]     = ((Ahh[0] + Ahl[0]) + Alh[0]) * SCALE_;
            S.sc[g4][j0+1]   = ((Ahh[1] + Ahl[1]) + Alh[1]) * SCALE_;
            S.sc[g4+8][j0]   = ((Ahh[2] + Ahl[2]) + Alh[2]) * SCALE_;
            S.sc[g4+8][j0+1] = ((Ahh[3] + Ahl[3]) + Alh[3]) * SCALE_;
        }
        buf ^= 1;
    }
    __syncthreads();

    if (split == 0 && t < 16) {
        if (g_sel[selbase] == 0) S.sc[t][0] += attn_sink[hbase + t];
    }
    __syncthreads();

    // ======== softmax partials (warp per 2 heads) ========
    {
        int jt = t & 31;
        #pragma unroll
        for (int hh = 0; hh < 2; hh++) {
            int hloc = 2*w + hh;
            float m = -3.4e38f;
            #pragma unroll
            for (int j = jt; j < 256; j += 32) m = fmaxf(m, S.sc[hloc][j]);
            #pragma unroll
            for (int o = 16; o; o >>= 1) m = fmaxf(m, __shfl_xor_sync(0xffffffffu, m, o));
            float sum = 0.f;
            #pragma unroll
            for (int j = jt; j < 256; j += 32) {
                float e = __expf(S.sc[hloc][j] - m);
                S.sc[hloc][j] = e;
                sum += e;
            }
            #pragma unroll
            for (int o = 16; o; o >>= 1) sum += __shfl_xor_sync(0xffffffffu, sum, o);
            if (jt == 0) g_pml[slot*16 + hloc] = make_float2(m, sum);
        }
    }

    // ======== phase C: O = P * K via tf32 MMA, 2 chains ========
    float acc0[4][2][4];   // hh chain
    float acc1[4][2][4];   // hl + lh chain
    #pragma unroll
    for (int cc = 0; cc < 4; cc++)
        #pragma unroll
        for (int nt = 0; nt < 2; nt++)
            #pragma unroll
            for (int r = 0; r < 4; r++) { acc0[cc][nt][r] = 0.f; acc1[cc][nt][r] = 0.f; }

    #pragma unroll 1
    for (int s = 0; s < 16; s++) {
        CP_WAIT0();
        __syncthreads();
        if (s < 15) {
            int ns = s + 1;
            prefetch_tile(S, buf^1, ns & 3, ns >> 2, selbase, kv, btbl, bq, t);
        }
        int ch = s >> 2, tile = s & 3;
        int kbase = tile << 6;
        const float* pa0 = &S.sc[g4][kbase + l4];
        const float* pa1 = &S.sc[g4+8][kbase + l4];
        const float* kbB = &S.k[buf][0][0];
        int r0base = l4;
        #pragma unroll
        for (int ks = 0; ks < 8; ks++) {
            int kc_ = ks << 3;
            float a0 = pa0[kc_];
            float a1 = pa1[kc_];
            float a2 = pa0[kc_ + 4];
            float a3 = pa1[kc_ + 4];
            unsigned ah0, ah1, ah2, ah3, al0, al1, al2, al3;
            SPLIT_HL(a0, ah0, al0); SPLIT_HL(a1, ah1, al1);
            SPLIT_HL(a2, ah2, al2); SPLIT_HL(a3, ah3, al3);
            int row0 = kc_ + r0base;
            int row1 = row0 + 4;
            const float* kr0 = kbB + (row0 << 7);
            const float* kr1 = kbB + (row1 << 7);
            int sw0 = row0 & 7, sw1 = row1 & 7;
            #pragma unroll
            for (int nt = 0; nt < 2; nt++) {
                int d = (w << 4) + (nt << 3) + g4;
                int dg = d >> 2, d3 = d & 3;
                float b0 = kr0[((dg ^ sw0) << 2) + d3];
                float b1 = kr1[((dg ^ sw1) << 2) + d3];
                unsigned bh0, bh1, bl0, bl1;
                SPLIT_HL(b0, bh0, bl0); SPLIT_HL(b1, bh1, bl1);
                float* C0 = acc0[ch][nt];
                float* C1 = acc1[ch][nt];
                mma_tf32(C1[0],C1[1],C1[2],C1[3], ah0,ah1,ah2,ah3, bl0,bl1);
                mma_tf32(C1[0],C1[1],C1[2],C1[3], al0,al1,al2,al3, bh0,bh1);
                mma_tf32(C0[0],C0[1],C0[2],C0[3], ah0,ah1,ah2,ah3, bh0,bh1);
            }
        }
        buf ^= 1;
    }

    {
        float* po = g_pO + ((size_t)slot*16)*ND_;
        #pragma unroll
        for (int cc = 0; cc < 4; cc++) {
            #pragma unroll
            for (int nt = 0; nt < 2; nt++) {
                int d = (cc << 7) + (w << 4) + (nt << 3) + (l4 << 1);
                float* C0 = acc0[cc][nt];
                float* C1 = acc1[cc][nt];
                *(float2*)(po + (size_t)g4*ND_ + d)     = make_float2(C0[0]+C1[0], C0[1]+C1[1]);
                *(float2*)(po + (size_t)(g4+8)*ND_ + d) = make_float2(C0[2]+C1[2], C0[3]+C1[3]);
            }
        }
    }
}

// ---------------- kernel 5: flash combine + optional key-0 term ----------------
__global__ void combine_kernel(const float* __restrict__ kv,
                               const float* __restrict__ attn_sink,
                               const int* __restrict__ btbl,
                               float* __restrict__ out) {
    __shared__ float k0s[512];
    __shared__ float s0sh[16];
    int hg = blockIdx.x, b = blockIdx.y;
    int t = threadIdx.x;
    int hbase = hg * 16;

    const float* k0 = kv + (size_t)btbl[b << 6] * (BS_ * ND_);
    {
        int i = t * 2;
        *(float2*)(k0s + i) = *(const float2*)(k0 + i);
    }
    __syncthreads();

    int h = t >> 4, ln = t & 15;
    {
        const float* qr = g_qr + ((size_t)b*NH_ + hbase + h)*ND_ + ln*32;
        const float* kk = k0s + ln*32;
        float acc = 0.f;
        #pragma unroll
        for (int i = 0; i < 32; i++) acc = fmaf(qr[i], kk[i], acc);
        #pragma unroll
        for (int o = 8; o; o >>= 1) acc += __shfl_xor_sync(0xffffffffu, acc, o);
        if (ln == 0) s0sh[h] = acc * SCALE_ + attn_sink[hbase + h];
    }
    __syncthreads();

    int dbase = ln * 32;
    int slot0 = (b*4 + hg)*2;
    float2 ml0 = g_pml[slot0*16 + h];
    float2 ml1 = g_pml[(slot0+1)*16 + h];
    int has0 = g_has0[b];
    float sc0 = s0sh[h];
    float M = fmaxf(ml0.x, ml1.x);
    if (!has0) M = fmaxf(M, sc0);
    float a0 = expf(ml0.x - M), a1 = expf(ml1.x - M);
    float a2 = has0 ? 0.f : expf(sc0 - M);
    float inv = 1.f / (ml0.y * a0 + ml1.y * a1 + a2);
    float c0 = a0 * inv, c1 = a1 * inv, c2 = a2 * inv;

    const float* p0 = g_pO + ((size_t)slot0*16 + h)*ND_ + dbase;
    const float* p1 = g_pO + ((size_t)(slot0+1)*16 + h)*ND_ + dbase;
    float* po = out + ((size_t)b*NH_ + hbase + h)*ND_ + dbase;
    #pragma unroll
    for (int i = 0; i < 8; i++) {
        float4 v0 = *(const float4*)(p0 + i*4);
        float4 v1 = *(const float4*)(p1 + i*4);
        float4 vk = *(const float4*)(k0s + dbase + i*4);
        float4 o;
        o.x = v0.x*c0 + v1.x*c1 + vk.x*c2;
        o.y = v0.y*c0 + v1.y*c1 + vk.y*c2;
        o.z = v0.z*c0 + v1.z*c1 + vk.z*c2;
        o.w = v0.w*c0 + v1.w*c1 + vk.w*c2;
        *(float4*)(po + i*4) = o;
    }
}

// ---------------- launch ----------------
extern "C" void kernel_launch(void* const* d_in, const int* in_sizes, int n_in,
                              void* d_out, int out_size) {
    const float* q      = (const float*)d_in[0];
    const float* cosp   = (const float*)d_in[1];
    const float* sinp   = (const float*)d_in[2];
    const float* kv     = (const float*)d_in[3];
    const float* q_idx  = (const float*)d_in[4];
    const float* k_idx  = (const float*)d_in[5];
    const float* sink   = (const float*)d_in[6];
    const int*   btbl   = (const int*)d_in[7];
    const int*   slens  = (const int*)d_in[8];
    float* out = (float*)d_out;

    prep_kernel<<<1280, 256>>>(q, cosp, sinp, q_idx);
    wsum_kernel<<<NB_, ID_>>>();
    indexer_kernel<<<dim3(16, NB_), 256>>>(k_idx, btbl, slens);
    topk_kernel<<<NB_, 1024>>>();

    int smem = (int)sizeof(AttnSmem);
    cudaFuncSetAttribute(attn_kernel, cudaFuncAttributeMaxDynamicSharedMemorySize, smem);
    attn_kernel<<<dim3(4, NB_, 2), 256, smem>>>(kv, sink, btbl);
    combine_kernel<<<dim3(4, NB_), 256>>>(kv, sink, btbl, out);
}

// round 15
// speedup vs baseline: 1.0358x; 1.0358x over previous
#include <cuda_runtime.h>
#include <cuda_bf16.h>
#include <math.h>
#include <stdint.h>

#define NB_  32
#define NH_  64
#define ND_  512
#define NROPE_ 64
#define NHALF_ 32
#define SMAX_ 4096
#define BS_  64
#define IH_  64
#define ID_  128
#define TOPK_ 512
#define SCALE_ 0.04419417382415922f

typedef unsigned long long ull;

// ---------------- scratch ----------------
__device__ float    g_qr[NB_*NH_*ND_];
__device__ unsigned g_qq[NB_*IH_*32];
__device__ float    g_qs[NB_*IH_];
__device__ float    g_w[NB_*ID_];
__device__ float    g_iscore[NB_*SMAX_];
__device__ int      g_sel[NB_*TOPK_];
__device__ int      g_has0[NB_];
__device__ float    g_pO[NB_*4*2*16*512];
__device__ float2   g_pml[NB_*4*2*16];

// ---------------- helpers ----------------
__device__ __forceinline__ void mma_tf32(float& c0, float& c1, float& c2, float& c3,
                                         unsigned a0, unsigned a1, unsigned a2, unsigned a3,
                                         unsigned b0, unsigned b1) {
    asm volatile("mma.sync.aligned.m16n8k8.row.col.f32.tf32.tf32.f32 "
        "{%0,%1,%2,%3}, {%4,%5,%6,%7}, {%8,%9}, {%0,%1,%2,%3};"
        : "+f"(c0), "+f"(c1), "+f"(c2), "+f"(c3)
        : "r"(a0), "r"(a1), "r"(a2), "r"(a3), "r"(b0), "r"(b1));
}

__device__ __forceinline__ void cpa16(void* dst_s, const void* src) {
    unsigned ds = (unsigned)__cvta_generic_to_shared(dst_s);
    asm volatile("cp.async.cg.shared.global [%0], [%1], 16;" :: "r"(ds), "l"(src));
}
#define CP_COMMIT() asm volatile("cp.async.commit_group;")
#define CP_WAIT0()  asm volatile("cp.async.wait_group 0;")

#define SPLIT_HL(x, hi, lo) do { \
    hi = __float_as_uint(x) & 0xFFFFE000u; \
    lo = __float_as_uint((x) - __uint_as_float(hi)); \
} while(0)

// ---------------- kernel 1: fused rope + q_idx quant ----------------
__device__ __forceinline__ int quant1(float x, float scale) {
    float r = rintf(x / scale);
    r = fminf(fmaxf(r, -128.f), 127.f);
    return (int)r;
}

__device__ __forceinline__ float quantf(float x, float scale) {
    float r = rintf(x / scale);
    return fminf(fmaxf(r, -128.f), 127.f);
}

__global__ void prep_kernel(const float* __restrict__ q,
                            const float* __restrict__ cosp,
                            const float* __restrict__ sinp,
                            const float* __restrict__ q_idx) {
    int t = threadIdx.x;
    if (blockIdx.x < 1024) {
        int bh = blockIdx.x * 2 + (t >> 7);
        int b  = bh >> 6;
        int d  = (t & 127) * 4;
        const float* src = q + (size_t)bh * ND_;
        float4 v = *(const float4*)(src + d);
        float4 o;
        if (d < ND_ - NROPE_) {
            o = v;
        } else {
            int i0 = (d - (ND_ - NROPE_)) >> 1;
            float c0 = cosp[b*NHALF_ + i0],   s0 = sinp[b*NHALF_ + i0];
            float c1 = cosp[b*NHALF_ + i0+1], s1 = sinp[b*NHALF_ + i0+1];
            o.x = v.x*c0 - v.y*s0;
            o.y = v.x*s0 + v.y*c0;
            o.z = v.z*c1 - v.w*s1;
            o.w = v.z*s1 + v.w*c1;
        }
        *(float4*)(g_qr + (size_t)bh*ND_ + d) = o;
    } else {
        int row  = (blockIdx.x - 1024) * 8 + (t >> 5);
        int lane = t & 31;
        float4 v = *(const float4*)(q_idx + (size_t)row*ID_ + lane*4);
        float m = fmaxf(fmaxf(fabsf(v.x), fabsf(v.y)), fmaxf(fabsf(v.z), fabsf(v.w)));
        #pragma unroll
        for (int o = 16; o; o >>= 1) m = fmaxf(m, __shfl_xor_sync(0xffffffffu, m, o));
        float scale = fmaxf(m, 1e-12f) * (1.f/127.f);
        if (scale < 1e-6f) scale = 1.f;
        int q0 = quant1(v.x, scale), q1 = quant1(v.y, scale);
        int q2 = quant1(v.z, scale), q3 = quant1(v.w, scale);
        unsigned w = (q0 & 0xFF) | ((q1 & 0xFF) << 8) | ((q2 & 0xFF) << 16) | ((q3 & 0xFF) << 24);
        g_qq[row*32 + lane] = w;
        if (lane == 0) g_qs[row] = scale;
    }
}

// ---------------- kernel 1b: w[b][d] = sum_h qs_h * qq_h[d] ----------------
__global__ void wsum_kernel() {
    int b = blockIdx.x;
    int d = threadIdx.x;
    int wi  = d >> 2;
    int wsh = (d & 3) << 3;
    float acc = 0.f;
    #pragma unroll 8
    for (int h = 0; h < IH_; h++) {
        unsigned wv = g_qq[(b*IH_ + h)*32 + wi];
        int c = (int)((signed char)((wv >> wsh) & 0xFFu));
        acc = fmaf((float)c, g_qs[b*IH_ + h], acc);
    }
    g_w[b*ID_ + d] = acc;
}

// ---------------- kernel 2: indexer, one 128-dot per key ----------------
__global__ void __launch_bounds__(256)
indexer_kernel(const float* __restrict__ k_idx_cache,
               const int* __restrict__ btbl,
               const int* __restrict__ seq_lens) {
    __shared__ float sw[ID_];
    int b = blockIdx.y, chunk = blockIdx.x;
    int t = threadIdx.x;
    if (t < ID_) sw[t] = g_w[b*ID_ + t];
    __syncthreads();

    int seqlen = seq_lens[b];
    int s = chunk*256 + t;
    int cs = min(s, seqlen-1);
    int pg = btbl[(b << 6) + (cs >> 6)];
    const float4* kr = (const float4*)(k_idx_cache + ((size_t)pg*BS_ + (cs & 63)) * ID_);

    float mx = 0.f;
    #pragma unroll
    for (int i = 0; i < 32; i++) {
        float4 v = kr[i];
        mx = fmaxf(mx, fmaxf(fmaxf(fabsf(v.x), fabsf(v.y)), fmaxf(fabsf(v.z), fabsf(v.w))));
    }
    float scale = fmaxf(mx, 1e-12f) * (1.f/127.f);
    if (scale < 1e-6f) scale = 1.f;

    float tot = 0.f;
    #pragma unroll
    for (int i = 0; i < 32; i++) {
        float4 v = kr[i];
        float q0 = quantf(v.x, scale);
        float q1 = quantf(v.y, scale);
        float q2 = quantf(v.z, scale);
        float q3 = quantf(v.w, scale);
        tot = fmaf(q0, sw[i*4+0], tot);
        tot = fmaf(q1, sw[i*4+1], tot);
        tot = fmaf(q2, sw[i*4+2], tot);
        tot = fmaf(q3, sw[i*4+3], tot);
    }
    g_iscore[b*SMAX_ + s] = (s < seqlen) ? tot * scale : __int_as_float(0xff800000);
}

// ---------------- kernel 3: exact top-k, 1024 threads ----------------
__device__ __forceinline__ int exscan1024(int v, int* sh, int* total) {
    int t = threadIdx.x, lane = t & 31, wid = t >> 5;
    __syncthreads();
    int incl = v;
    #pragma unroll
    for (int o = 1; o < 32; o <<= 1) {
        int n = __shfl_up_sync(0xffffffffu, incl, o);
        if (lane >= o) incl += n;
    }
    if (lane == 31) sh[wid] = incl;
    __syncthreads();
    if (wid == 0) {
        int x = sh[lane];
        #pragma unroll
        for (int o = 1; o < 32; o <<= 1) {
            int n = __shfl_up_sync(0xffffffffu, x, o);
            if (lane >= o) x += n;
        }
        sh[lane] = x;
    }
    __syncthreads();
    int base = wid ? sh[wid-1] : 0;
    *total = sh[31];
    return base + incl - v;
}

__device__ __forceinline__ void select_bin(int* hist, int* sscan, int* sinfo, int Krem) {
    int t = threadIdx.x, lane = t & 31, wid = t >> 5;
    int c = (t < 256) ? hist[t] : 0;
    int incl = c;
    #pragma unroll
    for (int o = 1; o < 32; o <<= 1) {
        int n = __shfl_up_sync(0xffffffffu, incl, o);
        if (lane >= o) incl += n;
    }
    if (lane == 31 && wid < 8) sscan[wid] = incl;
    __syncthreads();
    if (wid == 0) {
        int x = (lane < 8) ? sscan[lane] : 0;
        #pragma unroll
        for (int o = 1; o < 8; o <<= 1) {
            int n = __shfl_up_sync(0xffffffffu, x, o);
            if (lane >= o) x += n;
        }
        if (lane < 8) sscan[lane] = x;
        if (lane == 7) sinfo[2] = x;
    }
    __syncthreads();
    if (t < 256) {
        int P = incl + (wid ? sscan[wid-1] : 0);
        int above = sinfo[2] - P;
        if (above < Krem && Krem <= above + c) {
            sinfo[0] = t;
            sinfo[1] = Krem - above;
        }
    }
    __syncthreads();
}

__global__ void __launch_bounds__(1024)
topk_kernel() {
    int b = blockIdx.x;
    __shared__ unsigned skey[SMAX_];
    __shared__ unsigned cand[SMAX_];
    __shared__ int hist[256];
    __shared__ int sscan[33];
    __shared__ int sinfo[3];
    __shared__ int ccnt;
    int t = threadIdx.x;   // 1024 threads

    {
        int i = t * 4;
        float4 v = *(const float4*)(g_iscore + b*SMAX_ + i);
        #pragma unroll
        for (int j = 0; j < 4; j++) {
            unsigned u = __float_as_uint((&v.x)[j]);
            skey[i+j] = (u & 0x80000000u) ? ~u : (u | 0x80000000u);
        }
    }
    if (t == 0) ccnt = 0;
    if (t < 256) hist[t] = 0;
    __syncthreads();

    for (int i = t; i < SMAX_; i += 1024)
        atomicAdd((unsigned*)&hist[skey[i] >> 24], 1u);
    __syncthreads();
    select_bin(hist, sscan, sinfo, TOPK_);
    unsigned b1 = (unsigned)sinfo[0];
    unsigned prefix = b1 << 24;
    int Krem = sinfo[1];

    for (int i = t; i < SMAX_; i += 1024) {
        unsigned u = skey[i];
        if ((u >> 24) == b1) cand[atomicAdd((unsigned*)&ccnt, 1u)] = u;
    }
    __syncthreads();
    int L = ccnt;
    unsigned mask = 0xFF000000u;

    for (int shift = 16; shift >= 0; shift -= 8) {
        if (t < 256) hist[t] = 0;
        __syncthreads();
        for (int i = t; i < L; i += 1024) {
            unsigned u = cand[i];
            if ((u & mask) == prefix) atomicAdd((unsigned*)&hist[(u >> shift) & 255], 1u);
        }
        __syncthreads();
        select_bin(hist, sscan, sinfo, Krem);
        prefix |= ((unsigned)sinfo[0]) << shift;
        mask   |= 0xFFu << shift;
        Krem = sinfo[1];
    }
    unsigned T = prefix;
    int R = Krem;

    int base = t * 4;
    int eqc = 0;
    #pragma unroll
    for (int i = 0; i < 4; i++) eqc += (skey[base+i] == T);
    int tot;
    int eqoff = exscan1024(eqc, sscan, &tot);

    int kc = 0;
    unsigned kmask = 0;
    int er = eqoff;
    #pragma unroll
    for (int i = 0; i < 4; i++) {
        unsigned u = skey[base+i];
        bool eq = (u == T);
        bool kp = (u > T) || (eq && er < R);
        er += eq;
        if (base + i == 0) g_has0[b] = kp ? 1 : 0;
        kmask |= (unsigned)kp << i;
        kc += kp;
    }
    int koff = exscan1024(kc, sscan, &tot);
    int p = koff;
    #pragma unroll
    for (int i = 0; i < 4; i++) {
        if ((kmask >> i) & 1) g_sel[b*TOPK_ + p++] = base + i;
    }
}

// ---------------- kernel 4: split-KV attention; A and C on tf32 MMA (R13) ----------------
#define QSTR 516
#define SCSTR 260

struct AttnSmem {
    float q[16*QSTR];        // 33024
    float k[2][64][128];     // 65536 swizzled
    float sc[16][SCSTR];     // 16640
};                           // 115200 B

extern __shared__ char smem_raw[];

__device__ __forceinline__ void prefetch_tile(AttnSmem& S, int buf, int tile, int ch,
                                              int selbase,
                                              const float* __restrict__ kv,
                                              const int* __restrict__ btbl,
                                              int bq, int t) {
    int kbase = tile << 6;
    int g = t & 31;
    int dstg = g ^ ((t >> 5) & 7);
    #pragma unroll
    for (int i = 0; i < 8; i++) {
        int r = (t >> 5) + (i << 3);
        int sp = g_sel[selbase + kbase + r];
        int pg = btbl[bq + (sp >> 6)];
        const float* src = kv + ((size_t)pg*BS_ + (sp & 63)) * ND_ + (ch << 7) + (g << 2);
        cpa16(&S.k[buf][r][dstg << 2], src);
    }
    CP_COMMIT();
}

__global__ void __launch_bounds__(256, 2)
attn_kernel(const float* __restrict__ kv,
            const float* __restrict__ attn_sink,
            const int* __restrict__ btbl) {
    AttnSmem& S = *(AttnSmem*)smem_raw;
    int hg = blockIdx.x, b = blockIdx.y, split = blockIdx.z;
    int t = threadIdx.x;
    int hbase = hg * 16;
    int selbase = b*TOPK_ + split*256;
    int bq = b << 6;
    int slot = (b*4 + hg)*2 + split;

    {
        const float* qr = g_qr + ((size_t)b*NH_ + hbase) * ND_;
        for (int i = t*4; i < 16*ND_; i += 1024) {
            int row = i >> 9, col = i & 511;
            *(float4*)&S.q[row*QSTR + col] = *(const float4*)(qr + i);
        }
    }
    prefetch_tile(S, 0, 0, 0, selbase, kv, btbl, bq, t);
    __syncthreads();

    int w    = t >> 5;
    int lane = t & 31;
    int g4 = lane >> 2, l4 = lane & 3;

    // ======== phase A: scores via tf32 MMA (3-term split) ========
    float c0 = 0.f, c1 = 0.f, c2 = 0.f, c3 = 0.f;
    int buf = 0;
    int rloc = (w << 3) + g4;
    #pragma unroll 1
    for (int s = 0; s < 16; s++) {
        CP_WAIT0();
        __syncthreads();
        if (s < 15) prefetch_tile(S, buf^1, (s+1) >> 2, (s+1) & 3, selbase, kv, btbl, bq, t);
        else        prefetch_tile(S, buf^1, 0, 0, selbase, kv, btbl, bq, t);
        int tile = s >> 2, ch = s & 3;
        if (ch == 0) { c0 = 0.f; c1 = 0.f; c2 = 0.f; c3 = 0.f; }
        const float* kb  = &S.k[buf][rloc][0];
        const float* q0p = &S.q[g4*QSTR + (ch << 7) + l4];
        const float* q1p = &S.q[(g4+8)*QSTR + (ch << 7) + l4];
        #pragma unroll
        for (int ks = 0; ks < 16; ks++) {
            int k0 = ks << 3;
            float a0 = q0p[k0];
            float a1 = q1p[k0];
            float a2 = q0p[k0 + 4];
            float a3 = q1p[k0 + 4];
            int gb = k0 >> 2;
            float b0 = kb[((gb ^ g4) << 2) + l4];
            float b1 = kb[(((gb + 1) ^ g4) << 2) + l4];
            unsigned ah0, ah1, ah2, ah3, al0, al1, al2, al3, bh0, bh1, bl0, bl1;
            SPLIT_HL(a0, ah0, al0); SPLIT_HL(a1, ah1, al1);
            SPLIT_HL(a2, ah2, al2); SPLIT_HL(a3, ah3, al3);
            SPLIT_HL(b0, bh0, bl0); SPLIT_HL(b1, bh1, bl1);
            mma_tf32(c0,c1,c2,c3, ah0,ah1,ah2,ah3, bl0,bl1);
            mma_tf32(c0,c1,c2,c3, al0,al1,al2,al3, bh0,bh1);
            mma_tf32(c0,c1,c2,c3, ah0,ah1,ah2,ah3, bh0,bh1);
        }
        if (ch == 3) {
            int j0 = (tile << 6) + (w << 3) + (l4 << 1);
            S.sc[g4][j0]     = c0 * SCALE_;
            S.sc[g4][j0+1]   = c1 * SCALE_;
            S.sc[g4+8][j0]   = c2 * SCALE_;
            S.sc[g4+8][j0+1] = c3 * SCALE_;
        }
        buf ^= 1;
    }
    __syncthreads();

    if (split == 0 && t < 16) {
        if (g_sel[selbase] == 0) S.sc[t][0] += attn_sink[hbase + t];
    }
    __syncthreads();

    // ======== softmax partials (warp per 2 heads) ========
    {
        int jt = t & 31;
        #pragma unroll
        for (int hh = 0; hh < 2; hh++) {
            int hloc = 2*w + hh;
            float m = -3.4e38f;
            #pragma unroll
            for (int j = jt; j < 256; j += 32) m = fmaxf(m, S.sc[hloc][j]);
            #pragma unroll
            for (int o = 16; o; o >>= 1) m = fmaxf(m, __shfl_xor_sync(0xffffffffu, m, o));
            float sum = 0.f;
            #pragma unroll
            for (int j = jt; j < 256; j += 32) {
                float e = __expf(S.sc[hloc][j] - m);
                S.sc[hloc][j] = e;
                sum += e;
            }
            #pragma unroll
            for (int o = 16; o; o >>= 1) sum += __shfl_xor_sync(0xffffffffu, sum, o);
            if (jt == 0) g_pml[slot*16 + hloc] = make_float2(m, sum);
        }
    }

    // ======== phase C: O = P * K via tf32 MMA (3-term split) ========
    float acc[4][2][4];
    #pragma unroll
    for (int cc = 0; cc < 4; cc++)
        #pragma unroll
        for (int nt = 0; nt < 2; nt++)
            #pragma unroll
            for (int r = 0; r < 4; r++) acc[cc][nt][r] = 0.f;

    #pragma unroll 1
    for (int s = 0; s < 16; s++) {
        CP_WAIT0();
        __syncthreads();
        if (s < 15) {
            int ns = s + 1;
            prefetch_tile(S, buf^1, ns & 3, ns >> 2, selbase, kv, btbl, bq, t);
        }
        int ch = s >> 2, tile = s & 3;
        int kbase = tile << 6;
        const float* pa0 = &S.sc[g4][kbase + l4];
        const float* pa1 = &S.sc[g4+8][kbase + l4];
        const float* kbB = &S.k[buf][0][0];
        int r0base = l4;
        #pragma unroll
        for (int ks = 0; ks < 8; ks++) {
            int kc_ = ks << 3;
            float a0 = pa0[kc_];
            float a1 = pa1[kc_];
            float a2 = pa0[kc_ + 4];
            float a3 = pa1[kc_ + 4];
            unsigned ah0, ah1, ah2, ah3, al0, al1, al2, al3;
            SPLIT_HL(a0, ah0, al0); SPLIT_HL(a1, ah1, al1);
            SPLIT_HL(a2, ah2, al2); SPLIT_HL(a3, ah3, al3);
            int row0 = kc_ + r0base;
            int row1 = row0 + 4;
            const float* kr0 = kbB + (row0 << 7);
            const float* kr1 = kbB + (row1 << 7);
            int sw0 = row0 & 7, sw1 = row1 & 7;
            #pragma unroll
            for (int nt = 0; nt < 2; nt++) {
                int d = (w << 4) + (nt << 3) + g4;
                int dg = d >> 2, d3 = d & 3;
                float b0 = kr0[((dg ^ sw0) << 2) + d3];
                float b1 = kr1[((dg ^ sw1) << 2) + d3];
                unsigned bh0, bh1, bl0, bl1;
                SPLIT_HL(b0, bh0, bl0); SPLIT_HL(b1, bh1, bl1);
                float* C = acc[ch][nt];
                mma_tf32(C[0],C[1],C[2],C[3], ah0,ah1,ah2,ah3, bl0,bl1);
                mma_tf32(C[0],C[1],C[2],C[3], al0,al1,al2,al3, bh0,bh1);
                mma_tf32(C[0],C[1],C[2],C[3], ah0,ah1,ah2,ah3, bh0,bh1);
            }
        }
        buf ^= 1;
    }

    {
        float* po = g_pO + ((size_t)slot*16)*ND_;
        #pragma unroll
        for (int cc = 0; cc < 4; cc++) {
            #pragma unroll
            for (int nt = 0; nt < 2; nt++) {
                int d = (cc << 7) + (w << 4) + (nt << 3) + (l4 << 1);
                float* C = acc[cc][nt];
                *(float2*)(po + (size_t)g4*ND_ + d)     = make_float2(C[0], C[1]);
                *(float2*)(po + (size_t)(g4+8)*ND_ + d) = make_float2(C[2], C[3]);
            }
        }
    }
}

// ---------------- kernel 5: flash combine + optional key-0 term ----------------
__global__ void combine_kernel(const float* __restrict__ kv,
                               const float* __restrict__ attn_sink,
                               const int* __restrict__ btbl,
                               float* __restrict__ out) {
    __shared__ float k0s[512];
    __shared__ float s0sh[16];
    int hg = blockIdx.x, b = blockIdx.y;
    int t = threadIdx.x;
    int hbase = hg * 16;

    const float* k0 = kv + (size_t)btbl[b << 6] * (BS_ * ND_);
    {
        int i = t * 2;
        *(float2*)(k0s + i) = *(const float2*)(k0 + i);
    }
    __syncthreads();

    int h = t >> 4, ln = t & 15;
    {
        const float* qr = g_qr + ((size_t)b*NH_ + hbase + h)*ND_ + ln*32;
        const float* kk = k0s + ln*32;
        float acc = 0.f;
        #pragma unroll
        for (int i = 0; i < 32; i++) acc = fmaf(qr[i], kk[i], acc);
        #pragma unroll
        for (int o = 8; o; o >>= 1) acc += __shfl_xor_sync(0xffffffffu, acc, o);
        if (ln == 0) s0sh[h] = acc * SCALE_ + attn_sink[hbase + h];
    }
    __syncthreads();

    int dbase = ln * 32;
    int slot0 = (b*4 + hg)*2;
    float2 ml0 = g_pml[slot0*16 + h];
    float2 ml1 = g_pml[(slot0+1)*16 + h];
    int has0 = g_has0[b];
    float sc0 = s0sh[h];
    float M = fmaxf(ml0.x, ml1.x);
    if (!has0) M = fmaxf(M, sc0);
    float a0 = expf(ml0.x - M), a1 = expf(ml1.x - M);
    float a2 = has0 ? 0.f : expf(sc0 - M);
    float inv = 1.f / (ml0.y * a0 + ml1.y * a1 + a2);
    float c0 = a0 * inv, c1 = a1 * inv, c2 = a2 * inv;

    const float* p0 = g_pO + ((size_t)slot0*16 + h)*ND_ + dbase;
    const float* p1 = g_pO + ((size_t)(slot0+1)*16 + h)*ND_ + dbase;
    float* po = out + ((size_t)b*NH_ + hbase + h)*ND_ + dbase;
    #pragma unroll
    for (int i = 0; i < 8; i++) {
        float4 v0 = *(const float4*)(p0 + i*4);
        float4 v1 = *(const float4*)(p1 + i*4);
        float4 vk = *(const float4*)(k0s + dbase + i*4);
        float4 o;
        o.x = v0.x*c0 + v1.x*c1 + vk.x*c2;
        o.y = v0.y*c0 + v1.y*c1 + vk.y*c2;
        o.z = v0.z*c0 + v1.z*c1 + vk.z*c2;
        o.w = v0.w*c0 + v1.w*c1 + vk.w*c2;
        *(float4*)(po + i*4) = o;
    }
}

// ---------------- launch ----------------
extern "C" void kernel_launch(void* const* d_in, const int* in_sizes, int n_in,
                              void* d_out, int out_size) {
    const float* q      = (const float*)d_in[0];
    const float* cosp   = (const float*)d_in[1];
    const float* sinp   = (const float*)d_in[2];
    const float* kv     = (const float*)d_in[3];
    const float* q_idx  = (const float*)d_in[4];
    const float* k_idx  = (const float*)d_in[5];
    const float* sink   = (const float*)d_in[6];
    const int*   btbl   = (const int*)d_in[7];
    const int*   slens  = (const int*)d_in[8];
    float* out = (float*)d_out;

    prep_kernel<<<1280, 256>>>(q, cosp, sinp, q_idx);
    wsum_kernel<<<NB_, ID_>>>();
    indexer_kernel<<<dim3(16, NB_), 256>>>(k_idx, btbl, slens);
    topk_kernel<<<NB_, 1024>>>();

    int smem = (int)sizeof(AttnSmem);
    cudaFuncSetAttribute(attn_kernel, cudaFuncAttributeMaxDynamicSharedMemorySize, smem);
    attn_kernel<<<dim3(4, NB_, 2), 256, smem>>>(kv, sink, btbl);
    combine_kernel<<<dim3(4, NB_), 256>>>(kv, sink, btbl, out);
}

// round 17
// speedup vs baseline: 1.0780x; 1.0407x over previous
#include <cuda_runtime.h>
#include <cuda_bf16.h>
#include <math.h>
#include <stdint.h>

#define NB_  32
#define NH_  64
#define ND_  512
#define NROPE_ 64
#define NHALF_ 32
#define SMAX_ 4096
#define BS_  64
#define IH_  64
#define ID_  128
#define TOPK_ 512
#define SCALE_ 0.04419417382415922f

typedef unsigned long long ull;

// ---------------- scratch ----------------
__device__ float    g_qr[NB_*NH_*ND_];
__device__ unsigned g_qq[NB_*IH_*32];
__device__ float    g_qs[NB_*IH_];
__device__ float    g_w[NB_*ID_];
__device__ float    g_iscore[NB_*SMAX_];
__device__ int      g_sel[NB_*TOPK_];
__device__ int      g_has0[NB_];
__device__ float    g_pO[NB_*4*2*16*512];
__device__ float2   g_pml[NB_*4*2*16];

// ---------------- helpers ----------------
__device__ __forceinline__ void mma_tf32(float& c0, float& c1, float& c2, float& c3,
                                         unsigned a0, unsigned a1, unsigned a2, unsigned a3,
                                         unsigned b0, unsigned b1) {
    asm volatile("mma.sync.aligned.m16n8k8.row.col.f32.tf32.tf32.f32 "
        "{%0,%1,%2,%3}, {%4,%5,%6,%7}, {%8,%9}, {%0,%1,%2,%3};"
        : "+f"(c0), "+f"(c1), "+f"(c2), "+f"(c3)
        : "r"(a0), "r"(a1), "r"(a2), "r"(a3), "r"(b0), "r"(b1));
}

__device__ __forceinline__ void cpa16(void* dst_s, const void* src) {
    unsigned ds = (unsigned)__cvta_generic_to_shared(dst_s);
    asm volatile("cp.async.cg.shared.global [%0], [%1], 16;" :: "r"(ds), "l"(src));
}
#define CP_COMMIT() asm volatile("cp.async.commit_group;")
#define CP_WAIT0()  asm volatile("cp.async.wait_group 0;")

#define SPLIT_HL(x, hi, lo) do { \
    hi = __float_as_uint(x) & 0xFFFFE000u; \
    lo = __float_as_uint((x) - __uint_as_float(hi)); \
} while(0)

// ---------------- kernel 1: fused rope + q_idx quant ----------------
__device__ __forceinline__ int quant1(float x, float scale) {
    float r = rintf(x / scale);
    r = fminf(fmaxf(r, -128.f), 127.f);
    return (int)r;
}

__device__ __forceinline__ float quantf(float x, float scale) {
    float r = rintf(x / scale);
    return fminf(fmaxf(r, -128.f), 127.f);
}

__global__ void prep_kernel(const float* __restrict__ q,
                            const float* __restrict__ cosp,
                            const float* __restrict__ sinp,
                            const float* __restrict__ q_idx) {
    int t = threadIdx.x;
    if (blockIdx.x < 1024) {
        int bh = blockIdx.x * 2 + (t >> 7);
        int b  = bh >> 6;
        int d  = (t & 127) * 4;
        const float* src = q + (size_t)bh * ND_;
        float4 v = *(const float4*)(src + d);
        float4 o;
        if (d < ND_ - NROPE_) {
            o = v;
        } else {
            int i0 = (d - (ND_ - NROPE_)) >> 1;
            float c0 = cosp[b*NHALF_ + i0],   s0 = sinp[b*NHALF_ + i0];
            float c1 = cosp[b*NHALF_ + i0+1], s1 = sinp[b*NHALF_ + i0+1];
            o.x = v.x*c0 - v.y*s0;
            o.y = v.x*s0 + v.y*c0;
            o.z = v.z*c1 - v.w*s1;
            o.w = v.z*s1 + v.w*c1;
        }
        *(float4*)(g_qr + (size_t)bh*ND_ + d) = o;
    } else {
        int row  = (blockIdx.x - 1024) * 8 + (t >> 5);
        int lane = t & 31;
        float4 v = *(const float4*)(q_idx + (size_t)row*ID_ + lane*4);
        float m = fmaxf(fmaxf(fabsf(v.x), fabsf(v.y)), fmaxf(fabsf(v.z), fabsf(v.w)));
        #pragma unroll
        for (int o = 16; o; o >>= 1) m = fmaxf(m, __shfl_xor_sync(0xffffffffu, m, o));
        float scale = fmaxf(m, 1e-12f) * (1.f/127.f);
        if (scale < 1e-6f) scale = 1.f;
        int q0 = quant1(v.x, scale), q1 = quant1(v.y, scale);
        int q2 = quant1(v.z, scale), q3 = quant1(v.w, scale);
        unsigned w = (q0 & 0xFF) | ((q1 & 0xFF) << 8) | ((q2 & 0xFF) << 16) | ((q3 & 0xFF) << 24);
        g_qq[row*32 + lane] = w;
        if (lane == 0) g_qs[row] = scale;
    }
}

// ---------------- kernel 1b: w[b][d] = sum_h qs_h * qq_h[d] ----------------
__global__ void wsum_kernel() {
    int b = blockIdx.x;
    int d = threadIdx.x;
    int wi  = d >> 2;
    int wsh = (d & 3) << 3;
    float acc = 0.f;
    #pragma unroll 8
    for (int h = 0; h < IH_; h++) {
        unsigned wv = g_qq[(b*IH_ + h)*32 + wi];
        int c = (int)((signed char)((wv >> wsh) & 0xFFu));
        acc = fmaf((float)c, g_qs[b*IH_ + h], acc);
    }
    g_w[b*ID_ + d] = acc;
}

// ---------------- kernel 2: indexer, warp-per-key (coalesced rows) ----------------
__global__ void __launch_bounds__(256)
indexer_kernel(const float* __restrict__ k_idx_cache,
               const int* __restrict__ btbl,
               const int* __restrict__ seq_lens) {
    int b = blockIdx.y, chunk = blockIdx.x;
    int t = threadIdx.x;
    int lane = t & 31, w = t >> 5;

    // per-lane w coefficients (4 floats) held in registers
    float4 swv = *(const float4*)(g_w + b*ID_ + lane*4);
    int seqlen = seq_lens[b];
    int base = chunk*256 + (w << 5);
    const int* bt = btbl + (b << 6);

    float res = 0.f;
    #pragma unroll 4
    for (int i = 0; i < 32; i++) {
        int s = base + i;
        int cs = min(s, seqlen-1);
        int pg = bt[cs >> 6];
        float4 v = *((const float4*)(k_idx_cache + ((size_t)pg*BS_ + (cs & 63)) * ID_) + lane);

        float m = fmaxf(fmaxf(fabsf(v.x), fabsf(v.y)), fmaxf(fabsf(v.z), fabsf(v.w)));
        #pragma unroll
        for (int o = 16; o; o >>= 1) m = fmaxf(m, __shfl_xor_sync(0xffffffffu, m, o));
        float scale = fmaxf(m, 1e-12f) * (1.f/127.f);
        if (scale < 1e-6f) scale = 1.f;

        float tot;
        tot = quantf(v.x, scale) * swv.x;
        tot = fmaf(quantf(v.y, scale), swv.y, tot);
        tot = fmaf(quantf(v.z, scale), swv.z, tot);
        tot = fmaf(quantf(v.w, scale), swv.w, tot);
        #pragma unroll
        for (int o = 16; o; o >>= 1) tot += __shfl_xor_sync(0xffffffffu, tot, o);

        if (lane == i) res = tot * scale;
    }

    int ss = base + lane;
    g_iscore[b*SMAX_ + ss] = (ss < seqlen) ? res : __int_as_float(0xff800000);
}

// ---------------- kernel 3: exact top-k, 1024 threads ----------------
__device__ __forceinline__ int exscan1024(int v, int* sh, int* total) {
    int t = threadIdx.x, lane = t & 31, wid = t >> 5;
    __syncthreads();
    int incl = v;
    #pragma unroll
    for (int o = 1; o < 32; o <<= 1) {
        int n = __shfl_up_sync(0xffffffffu, incl, o);
        if (lane >= o) incl += n;
    }
    if (lane == 31) sh[wid] = incl;
    __syncthreads();
    if (wid == 0) {
        int x = sh[lane];
        #pragma unroll
        for (int o = 1; o < 32; o <<= 1) {
            int n = __shfl_up_sync(0xffffffffu, x, o);
            if (lane >= o) x += n;
        }
        sh[lane] = x;
    }
    __syncthreads();
    int base = wid ? sh[wid-1] : 0;
    *total = sh[31];
    return base + incl - v;
}

__device__ __forceinline__ void select_bin(int* hist, int* sscan, int* sinfo, int Krem) {
    int t = threadIdx.x, lane = t & 31, wid = t >> 5;
    int c = (t < 256) ? hist[t] : 0;
    int incl = c;
    #pragma unroll
    for (int o = 1; o < 32; o <<= 1) {
        int n = __shfl_up_sync(0xffffffffu, incl, o);
        if (lane >= o) incl += n;
    }
    if (lane == 31 && wid < 8) sscan[wid] = incl;
    __syncthreads();
    if (wid == 0) {
        int x = (lane < 8) ? sscan[lane] : 0;
        #pragma unroll
        for (int o = 1; o < 8; o <<= 1) {
            int n = __shfl_up_sync(0xffffffffu, x, o);
            if (lane >= o) x += n;
        }
        if (lane < 8) sscan[lane] = x;
        if (lane == 7) sinfo[2] = x;
    }
    __syncthreads();
    if (t < 256) {
        int P = incl + (wid ? sscan[wid-1] : 0);
        int above = sinfo[2] - P;
        if (above < Krem && Krem <= above + c) {
            sinfo[0] = t;
            sinfo[1] = Krem - above;
        }
    }
    __syncthreads();
}

__global__ void __launch_bounds__(1024)
topk_kernel() {
    int b = blockIdx.x;
    __shared__ unsigned skey[SMAX_];
    __shared__ unsigned cand[SMAX_];
    __shared__ int hist[256];
    __shared__ int sscan[33];
    __shared__ int sinfo[3];
    __shared__ int ccnt;
    int t = threadIdx.x;   // 1024 threads

    {
        int i = t * 4;
        float4 v = *(const float4*)(g_iscore + b*SMAX_ + i);
        #pragma unroll
        for (int j = 0; j < 4; j++) {
            unsigned u = __float_as_uint((&v.x)[j]);
            skey[i+j] = (u & 0x80000000u) ? ~u : (u | 0x80000000u);
        }
    }
    if (t == 0) ccnt = 0;
    if (t < 256) hist[t] = 0;
    __syncthreads();

    for (int i = t; i < SMAX_; i += 1024)
        atomicAdd((unsigned*)&hist[skey[i] >> 24], 1u);
    __syncthreads();
    select_bin(hist, sscan, sinfo, TOPK_);
    unsigned b1 = (unsigned)sinfo[0];
    unsigned prefix = b1 << 24;
    int Krem = sinfo[1];

    for (int i = t; i < SMAX_; i += 1024) {
        unsigned u = skey[i];
        if ((u >> 24) == b1) cand[atomicAdd((unsigned*)&ccnt, 1u)] = u;
    }
    __syncthreads();
    int L = ccnt;
    unsigned mask = 0xFF000000u;

    for (int shift = 16; shift >= 0; shift -= 8) {
        if (t < 256) hist[t] = 0;
        __syncthreads();
        for (int i = t; i < L; i += 1024) {
            unsigned u = cand[i];
            if ((u & mask) == prefix) atomicAdd((unsigned*)&hist[(u >> shift) & 255], 1u);
        }
        __syncthreads();
        select_bin(hist, sscan, sinfo, Krem);
        prefix |= ((unsigned)sinfo[0]) << shift;
        mask   |= 0xFFu << shift;
        Krem = sinfo[1];
    }
    unsigned T = prefix;
    int R = Krem;

    int base = t * 4;
    int eqc = 0;
    #pragma unroll
    for (int i = 0; i < 4; i++) eqc += (skey[base+i] == T);
    int tot;
    int eqoff = exscan1024(eqc, sscan, &tot);

    int kc = 0;
    unsigned kmask = 0;
    int er = eqoff;
    #pragma unroll
    for (int i = 0; i < 4; i++) {
        unsigned u = skey[base+i];
        bool eq = (u == T);
        bool kp = (u > T) || (eq && er < R);
        er += eq;
        if (base + i == 0) g_has0[b] = kp ? 1 : 0;
        kmask |= (unsigned)kp << i;
        kc += kp;
    }
    int koff = exscan1024(kc, sscan, &tot);
    int p = koff;
    #pragma unroll
    for (int i = 0; i < 4; i++) {
        if ((kmask >> i) & 1) g_sel[b*TOPK_ + p++] = base + i;
    }
}

// ---------------- kernel 4: split-KV attention; A and C on tf32 MMA (R13) ----------------
#define QSTR 516
#define SCSTR 260

struct AttnSmem {
    float q[16*QSTR];        // 33024
    float k[2][64][128];     // 65536 swizzled
    float sc[16][SCSTR];     // 16640
};                           // 115200 B

extern __shared__ char smem_raw[];

__device__ __forceinline__ void prefetch_tile(AttnSmem& S, int buf, int tile, int ch,
                                              int selbase,
                                              const float* __restrict__ kv,
                                              const int* __restrict__ btbl,
                                              int bq, int t) {
    int kbase = tile << 6;
    int g = t & 31;
    int dstg = g ^ ((t >> 5) & 7);
    #pragma unroll
    for (int i = 0; i < 8; i++) {
        int r = (t >> 5) + (i << 3);
        int sp = g_sel[selbase + kbase + r];
        int pg = btbl[bq + (sp >> 6)];
        const float* src = kv + ((size_t)pg*BS_ + (sp & 63)) * ND_ + (ch << 7) + (g << 2);
        cpa16(&S.k[buf][r][dstg << 2], src);
    }
    CP_COMMIT();
}

__global__ void __launch_bounds__(256, 2)
attn_kernel(const float* __restrict__ kv,
            const float* __restrict__ attn_sink,
            const int* __restrict__ btbl) {
    AttnSmem& S = *(AttnSmem*)smem_raw;
    int hg = blockIdx.x, b = blockIdx.y, split = blockIdx.z;
    int t = threadIdx.x;
    int hbase = hg * 16;
    int selbase = b*TOPK_ + split*256;
    int bq = b << 6;
    int slot = (b*4 + hg)*2 + split;

    {
        const float* qr = g_qr + ((size_t)b*NH_ + hbase) * ND_;
        for (int i = t*4; i < 16*ND_; i += 1024) {
            int row = i >> 9, col = i & 511;
            *(float4*)&S.q[row*QSTR + col] = *(const float4*)(qr + i);
        }
    }
    prefetch_tile(S, 0, 0, 0, selbase, kv, btbl, bq, t);
    __syncthreads();

    int w    = t >> 5;
    int lane = t & 31;
    int g4 = lane >> 2, l4 = lane & 3;

    // ======== phase A: scores via tf32 MMA (3-term split) ========
    float c0 = 0.f, c1 = 0.f, c2 = 0.f, c3 = 0.f;
    int buf = 0;
    int rloc = (w << 3) + g4;
    #pragma unroll 1
    for (int s = 0; s < 16; s++) {
        CP_WAIT0();
        __syncthreads();
        if (s < 15) prefetch_tile(S, buf^1, (s+1) >> 2, (s+1) & 3, selbase, kv, btbl, bq, t);
        else        prefetch_tile(S, buf^1, 0, 0, selbase, kv, btbl, bq, t);
        int tile = s >> 2, ch = s & 3;
        if (ch == 0) { c0 = 0.f; c1 = 0.f; c2 = 0.f; c3 = 0.f; }
        const float* kb  = &S.k[buf][rloc][0];
        const float* q0p = &S.q[g4*QSTR + (ch << 7) + l4];
        const float* q1p = &S.q[(g4+8)*QSTR + (ch << 7) + l4];
        #pragma unroll
        for (int ks = 0; ks < 16; ks++) {
            int k0 = ks << 3;
            float a0 = q0p[k0];
            float a1 = q1p[k0];
            float a2 = q0p[k0 + 4];
            float a3 = q1p[k0 + 4];
            int gb = k0 >> 2;
            float b0 = kb[((gb ^ g4) << 2) + l4];
            float b1 = kb[(((gb + 1) ^ g4) << 2) + l4];
            unsigned ah0, ah1, ah2, ah3, al0, al1, al2, al3, bh0, bh1, bl0, bl1;
            SPLIT_HL(a0, ah0, al0); SPLIT_HL(a1, ah1, al1);
            SPLIT_HL(a2, ah2, al2); SPLIT_HL(a3, ah3, al3);
            SPLIT_HL(b0, bh0, bl0); SPLIT_HL(b1, bh1, bl1);
            mma_tf32(c0,c1,c2,c3, ah0,ah1,ah2,ah3, bl0,bl1);
            mma_tf32(c0,c1,c2,c3, al0,al1,al2,al3, bh0,bh1);
            mma_tf32(c0,c1,c2,c3, ah0,ah1,ah2,ah3, bh0,bh1);
        }
        if (ch == 3) {
            int j0 = (tile << 6) + (w << 3) + (l4 << 1);
            S.sc[g4][j0]     = c0 * SCALE_;
            S.sc[g4][j0+1]   = c1 * SCALE_;
            S.sc[g4+8][j0]   = c2 * SCALE_;
            S.sc[g4+8][j0+1] = c3 * SCALE_;
        }
        buf ^= 1;
    }
    __syncthreads();

    if (split == 0 && t < 16) {
        if (g_sel[selbase] == 0) S.sc[t][0] += attn_sink[hbase + t];
    }
    __syncthreads();

    // ======== softmax partials (warp per 2 heads) ========
    {
        int jt = t & 31;
        #pragma unroll
        for (int hh = 0; hh < 2; hh++) {
            int hloc = 2*w + hh;
            float m = -3.4e38f;
            #pragma unroll
            for (int j = jt; j < 256; j += 32) m = fmaxf(m, S.sc[hloc][j]);
            #pragma unroll
            for (int o = 16; o; o >>= 1) m = fmaxf(m, __shfl_xor_sync(0xffffffffu, m, o));
            float sum = 0.f;
            #pragma unroll
            for (int j = jt; j < 256; j += 32) {
                float e = __expf(S.sc[hloc][j] - m);
                S.sc[hloc][j] = e;
                sum += e;
            }
            #pragma unroll
            for (int o = 16; o; o >>= 1) sum += __shfl_xor_sync(0xffffffffu, sum, o);
            if (jt == 0) g_pml[slot*16 + hloc] = make_float2(m, sum);
        }
    }

    // ======== phase C: O = P * K via tf32 MMA (3-term split) ========
    float acc[4][2][4];
    #pragma unroll
    for (int cc = 0; cc < 4; cc++)
        #pragma unroll
        for (int nt = 0; nt < 2; nt++)
            #pragma unroll
            for (int r = 0; r < 4; r++) acc[cc][nt][r] = 0.f;

    #pragma unroll 1
    for (int s = 0; s < 16; s++) {
        CP_WAIT0();
        __syncthreads();
        if (s < 15) {
            int ns = s + 1;
            prefetch_tile(S, buf^1, ns & 3, ns >> 2, selbase, kv, btbl, bq, t);
        }
        int ch = s >> 2, tile = s & 3;
        int kbase = tile << 6;
        const float* pa0 = &S.sc[g4][kbase + l4];
        const float* pa1 = &S.sc[g4+8][kbase + l4];
        const float* kbB = &S.k[buf][0][0];
        int r0base = l4;
        #pragma unroll
        for (int ks = 0; ks < 8; ks++) {
            int kc_ = ks << 3;
            float a0 = pa0[kc_];
            float a1 = pa1[kc_];
            float a2 = pa0[kc_ + 4];
            float a3 = pa1[kc_ + 4];
            unsigned ah0, ah1, ah2, ah3, al0, al1, al2, al3;
            SPLIT_HL(a0, ah0, al0); SPLIT_HL(a1, ah1, al1);
            SPLIT_HL(a2, ah2, al2); SPLIT_HL(a3, ah3, al3);
            int row0 = kc_ + r0base;
            int row1 = row0 + 4;
            const float* kr0 = kbB + (row0 << 7);
            const float* kr1 = kbB + (row1 << 7);
            int sw0 = row0 & 7, sw1 = row1 & 7;
            #pragma unroll
            for (int nt = 0; nt < 2; nt++) {
                int d = (w << 4) + (nt << 3) + g4;
                int dg = d >> 2, d3 = d & 3;
                float b0 = kr0[((dg ^ sw0) << 2) + d3];
                float b1 = kr1[((dg ^ sw1) << 2) + d3];
                unsigned bh0, bh1, bl0, bl1;
                SPLIT_HL(b0, bh0, bl0); SPLIT_HL(b1, bh1, bl1);
                float* C = acc[ch][nt];
                mma_tf32(C[0],C[1],C[2],C[3], ah0,ah1,ah2,ah3, bl0,bl1);
                mma_tf32(C[0],C[1],C[2],C[3], al0,al1,al2,al3, bh0,bh1);
                mma_tf32(C[0],C[1],C[2],C[3], ah0,ah1,ah2,ah3, bh0,bh1);
            }
        }
        buf ^= 1;
    }

    {
        float* po = g_pO + ((size_t)slot*16)*ND_;
        #pragma unroll
        for (int cc = 0; cc < 4; cc++) {
            #pragma unroll
            for (int nt = 0; nt < 2; nt++) {
                int d = (cc << 7) + (w << 4) + (nt << 3) + (l4 << 1);
                float* C = acc[cc][nt];
                *(float2*)(po + (size_t)g4*ND_ + d)     = make_float2(C[0], C[1]);
                *(float2*)(po + (size_t)(g4+8)*ND_ + d) = make_float2(C[2], C[3]);
            }
        }
    }
}

// ---------------- kernel 5: flash combine + optional key-0 term ----------------
__global__ void combine_kernel(const float* __restrict__ kv,
                               const float* __restrict__ attn_sink,
                               const int* __restrict__ btbl,
                               float* __restrict__ out) {
    __shared__ float k0s[512];
    __shared__ float s0sh[16];
    int hg = blockIdx.x, b = blockIdx.y;
    int t = threadIdx.x;
    int hbase = hg * 16;

    const float* k0 = kv + (size_t)btbl[b << 6] * (BS_ * ND_);
    {
        int i = t * 2;
        *(float2*)(k0s + i) = *(const float2*)(k0 + i);
    }
    __syncthreads();

    int h = t >> 4, ln = t & 15;
    {
        const float* qr = g_qr + ((size_t)b*NH_ + hbase + h)*ND_ + ln*32;
        const float* kk = k0s + ln*32;
        float acc = 0.f;
        #pragma unroll
        for (int i = 0; i < 32; i++) acc = fmaf(qr[i], kk[i], acc);
        #pragma unroll
        for (int o = 8; o; o >>= 1) acc += __shfl_xor_sync(0xffffffffu, acc, o);
        if (ln == 0) s0sh[h] = acc * SCALE_ + attn_sink[hbase + h];
    }
    __syncthreads();

    int dbase = ln * 32;
    int slot0 = (b*4 + hg)*2;
    float2 ml0 = g_pml[slot0*16 + h];
    float2 ml1 = g_pml[(slot0+1)*16 + h];
    int has0 = g_has0[b];
    float sc0 = s0sh[h];
    float M = fmaxf(ml0.x, ml1.x);
    if (!has0) M = fmaxf(M, sc0);
    float a0 = expf(ml0.x - M), a1 = expf(ml1.x - M);
    float a2 = has0 ? 0.f : expf(sc0 - M);
    float inv = 1.f / (ml0.y * a0 + ml1.y * a1 + a2);
    float c0 = a0 * inv, c1 = a1 * inv, c2 = a2 * inv;

    const float* p0 = g_pO + ((size_t)slot0*16 + h)*ND_ + dbase;
    const float* p1 = g_pO + ((size_t)(slot0+1)*16 + h)*ND_ + dbase;
    float* po = out + ((size_t)b*NH_ + hbase + h)*ND_ + dbase;
    #pragma unroll
    for (int i = 0; i < 8; i++) {
        float4 v0 = *(const float4*)(p0 + i*4);
        float4 v1 = *(const float4*)(p1 + i*4);
        float4 vk = *(const float4*)(k0s + dbase + i*4);
        float4 o;
        o.x = v0.x*c0 + v1.x*c1 + vk.x*c2;
        o.y = v0.y*c0 + v1.y*c1 + vk.y*c2;
        o.z = v0.z*c0 + v1.z*c1 + vk.z*c2;
        o.w = v0.w*c0 + v1.w*c1 + vk.w*c2;
        *(float4*)(po + i*4) = o;
    }
}

// ---------------- launch ----------------
extern "C" void kernel_launch(void* const* d_in, const int* in_sizes, int n_in,
                              void* d_out, int out_size) {
    const float* q      = (const float*)d_in[0];
    const float* cosp   = (const float*)d_in[1];
    const float* sinp   = (const float*)d_in[2];
    const float* kv     = (const float*)d_in[3];
    const float* q_idx  = (const float*)d_in[4];
    const float* k_idx  = (const float*)d_in[5];
    const float* sink   = (const float*)d_in[6];
    const int*   btbl   = (const int*)d_in[7];
    const int*   slens  = (const int*)d_in[8];
    float* out = (float*)d_out;

    prep_kernel<<<1280, 256>>>(q, cosp, sinp, q_idx);
    wsum_kernel<<<NB_, ID_>>>();
    indexer_kernel<<<dim3(16, NB_), 256>>>(k_idx, btbl, slens);
    topk_kernel<<<NB_, 1024>>>();

    int smem = (int)sizeof(AttnSmem);
    cudaFuncSetAttribute(attn_kernel, cudaFuncAttributeMaxDynamicSharedMemorySize, smem);
    attn_kernel<<<dim3(4, NB_, 2), 256, smem>>>(kv, sink, btbl);
    combine_kernel<<<dim3(4, NB_), 256>>>(kv, sink, btbl, out);
}